// round 6
// baseline (speedup 1.0000x reference)
#include <cuda_runtime.h>
#include <cstdint>

#define TSTEPS 1024
#define BATCH  256
#define INSZ   128
#define HID    512
#define OUTSZ  32
#define RB     16      // batch rows per cluster
#define JT     64      // hidden outputs per CTA
#define CLUSZ  8       // CTAs per cluster
#define THR2   1024    // threads per rnn CTA
#define NSEG   16      // k-segments (32 wide each)

// scratch (device globals: the sanctioned no-alloc workaround)
__device__ float g_xproj[(size_t)TSTEPS * BATCH * HID];   // 512 MB
__device__ float g_h[2][BATCH * HID];                     // double-buffered state

// ---------------- packed f32x2 helpers (sm_103a FFMA2) ----------------
__device__ __forceinline__ void fma2(unsigned long long& d,
                                     unsigned long long a,
                                     unsigned long long b) {
    asm("fma.rn.f32x2 %0, %1, %2, %0;" : "+l"(d) : "l"(a), "l"(b));
}
__device__ __forceinline__ unsigned long long splat2(float a) {
    unsigned long long r;
    asm("mov.b64 %0, {%1, %1};" : "=l"(r) : "f"(a));
    return r;
}
__device__ __forceinline__ float2 unpk(unsigned long long v) {
    float2 f;
    asm("mov.b64 {%0, %1}, %2;" : "=f"(f.x), "=f"(f.y) : "l"(v));
    return f;
}

// ---------------------------------------------------------------------------
// Kernel 1: x_proj[t,b,:] = inputs[t,b,:] @ W_in + b_rec   (M=262144,K=128,N=512)
// ---------------------------------------------------------------------------
__global__ void __launch_bounds__(256, 1)
xproj_kernel(const float* __restrict__ in, const float* __restrict__ Win,
             const float* __restrict__ brec)
{
    extern __shared__ float sm1[];
    float*  As  = sm1;               // [128][132] padded
    float4* As4 = (float4*)As;
    float*  Bs  = sm1 + 128 * 132;   // [128][128]
    float4* Bs4 = (float4*)Bs;

    const int tid = threadIdx.x;
    const int m0  = blockIdx.x * 128;
    const int n0  = blockIdx.y * 128;

    for (int i = tid; i < 4096; i += 256) {
        int m = i >> 5, kq = i & 31;
        As4[m * 33 + kq] = *(const float4*)(in + (size_t)(m0 + m) * INSZ + kq * 4);
    }
    for (int i = tid; i < 4096; i += 256) {
        int k = i >> 5, nq = i & 31;
        Bs4[k * 32 + nq] = *(const float4*)(Win + (size_t)k * HID + n0 + nq * 4);
    }
    __syncthreads();

    const int tx = tid & 15, ty = tid >> 4;
    const int mm = ty * 8,   nn = tx * 8;

    unsigned long long accq[8][4];
#pragma unroll
    for (int i = 0; i < 8; i++)
#pragma unroll
        for (int jj = 0; jj < 4; jj++) accq[i][jj] = 0ULL;

#pragma unroll 4
    for (int k = 0; k < 128; k++) {
        unsigned long long aa[8];
#pragma unroll
        for (int i = 0; i < 8; i++) aa[i] = splat2(As[(mm + i) * 132 + k]);
        const ulonglong2* bq = (const ulonglong2*)(Bs4 + k * 32 + (nn >> 2));
        ulonglong2 bA = bq[0];
        ulonglong2 bB = bq[1];
#pragma unroll
        for (int i = 0; i < 8; i++) {
            fma2(accq[i][0], aa[i], bA.x);
            fma2(accq[i][1], aa[i], bA.y);
            fma2(accq[i][2], aa[i], bB.x);
            fma2(accq[i][3], aa[i], bB.y);
        }
    }

    float4 br0 = *(const float4*)(brec + n0 + nn);
    float4 br1 = *(const float4*)(brec + n0 + nn + 4);
#pragma unroll
    for (int i = 0; i < 8; i++) {
        float2 p0 = unpk(accq[i][0]), p1 = unpk(accq[i][1]);
        float2 p2 = unpk(accq[i][2]), p3 = unpk(accq[i][3]);
        float4 s0 = make_float4(p0.x + br0.x, p0.y + br0.y, p1.x + br0.z, p1.y + br0.w);
        float4 s1 = make_float4(p2.x + br1.x, p2.y + br1.y, p3.x + br1.z, p3.y + br1.w);
        float* dst = g_xproj + (size_t)(m0 + mm + i) * HID + n0 + nn;
        *(float4*)dst       = s0;
        *(float4*)(dst + 4) = s1;
    }
}

// ---------------------------------------------------------------------------
// Kernel 2: persistent recurrence + fused output projection, 1024 threads/CTA.
// grid = 128 CTAs = 16 clusters x 8; cluster c owns batch rows [16c, 16c+16);
// CTA rank r owns hidden slice [64r, 64r+64). Thread (j = tid&63,
// kseg = tid>>6 in [0,16)) holds W_rec[jbase+j][kseg*32 .. +32) in 32 regs.
// Cluster barrier is split arrive/wait with the output projection overlapped.
// ---------------------------------------------------------------------------
// smem layout (floats)
#define SM2_H     0                        // [16][512]            8192
#define SM2_PART  (16 * 512)               // [16][16][64]        16384
#define SM2_OPART (SM2_PART + 16384)       // [16][64]             1024
#define SM2_XP    (SM2_OPART + 1024)       // [16][64]             1024
#define SM2_WOUT  (SM2_XP + 1024)          // [512][32]           16384
#define SM2_BOUT  (SM2_WOUT + 16384)       // [32]
#define SM2_BYTES ((SM2_BOUT + 32) * 4)    // 172160 bytes

__global__ void __cluster_dims__(CLUSZ, 1, 1) __launch_bounds__(THR2, 1)
rnn_kernel(const float* __restrict__ Wrec, const float* __restrict__ Wout,
           const float* __restrict__ bout, float* __restrict__ out)
{
    extern __shared__ float sm[];
    float*  sh_h     = sm + SM2_H;
    float4* sh_h4    = (float4*)sh_h;
    float*  sh_part  = sm + SM2_PART;
    float*  sh_opart = sm + SM2_OPART;
    float*  sh_xp    = sm + SM2_XP;
    float*  sh_wout  = sm + SM2_WOUT;
    float*  sh_bout  = sm + SM2_BOUT;

    const int tid   = threadIdx.x;
    const int rank  = blockIdx.x & (CLUSZ - 1);
    const int clu   = blockIdx.x >> 3;
    const int b0    = clu * RB;
    const int jbase = rank * JT;

    const int j    = tid & 63;
    const int kseg = tid >> 6;           // 16 k-segments of 32

    // resident W_rec slice: 32 floats = 16 f32x2 pairs = 8 ulonglong2 (32 regs)
    ulonglong2 W2[8];
    {
        const ulonglong2* wr =
            (const ulonglong2*)(Wrec + (size_t)(jbase + j) * HID + kseg * 32);
#pragma unroll
        for (int q = 0; q < 8; q++) W2[q] = wr[q];
    }
    // W_out / b_out to smem (consumed from s=1 on; first syncthreads covers it)
    {
        const float4* wg = (const float4*)Wout;
        float4* ws = (float4*)sh_wout;
        for (int i = tid; i < HID * OUTSZ / 4; i += THR2) ws[i] = wg[i];
        if (tid < OUTSZ) sh_bout[tid] = bout[tid];
    }

    // output-projection mapping: 2 rows x 32 outs per rank, 16-way k-split (32 each)
    const int orow_el    = tid & 63;
    const int oo         = orow_el & 31;
    const int orow_local = 2 * rank + (orow_el >> 5);
    const int oksub      = tid >> 6;

    // xp prefetch: threads < 256 each hold one float4 of the [16][64] tile
    const int xb = tid >> 4, xq = tid & 15;
    float4 xpr = make_float4(0.f, 0.f, 0.f, 0.f);
    if (tid < 256)
        xpr = *(const float4*)(g_xproj + ((size_t)0 * BATCH + b0 + xb) * HID
                               + jbase + xq * 4);

    for (int s = 0; s < TSTEPS; ++s) {
        // ---- load H_s (full 16x512 = 2048 float4; 2 per thread) ----
        if (s == 0) {
            float4 z = make_float4(0.f, 0.f, 0.f, 0.f);
            sh_h4[tid]        = z;
            sh_h4[tid + THR2] = z;
        } else {
            const float4* hs = (const float4*)(g_h[s & 1] + (size_t)b0 * HID);
            sh_h4[tid]        = __ldcv(hs + tid);
            sh_h4[tid + THR2] = __ldcv(hs + tid + THR2);
        }
        // publish prefetched xp, then start prefetch for s+1 (hidden by compute)
        if (tid < 256) {
            ((float4*)sh_xp)[tid] = xpr;
            if (s + 1 < TSTEPS)
                xpr = *(const float4*)(g_xproj + ((size_t)(s + 1) * BATCH + b0 + xb) * HID
                                       + jbase + xq * 4);
        }
        __syncthreads();

        // ---- recurrent matmul partials: pre[b][j] over this 32-wide k-segment ----
        {
            const float* hbase = sh_h + kseg * 32;
#pragma unroll 2
            for (int b = 0; b < RB; b++) {
                const ulonglong2* hrow = (const ulonglong2*)(hbase + b * HID);
                unsigned long long a01 = 0ULL, a23 = 0ULL;
#pragma unroll
                for (int q = 0; q < 8; q++) {
                    ulonglong2 hv = hrow[q];
                    fma2(a01, W2[q].x, hv.x);
                    fma2(a23, W2[q].y, hv.y);
                }
                float2 u = unpk(a01), v = unpk(a23);
                sh_part[(b * NSEG + kseg) * 64 + j] = (u.x + u.y) + (v.x + v.y);
            }
        }
        __syncthreads();

        // ---- state update: H_{s+1}, one (b,j) element per thread ----
        {
            const int b = tid >> 6;          // j = tid & 63 (already computed)
            float pre = 0.f;
#pragma unroll
            for (int k = 0; k < NSEG; k++)
                pre += sh_part[(b * NSEG + k) * 64 + j];
            float act = pre + sh_xp[b * 64 + j];
            act = act > 0.f ? act : 0.f;
            float hn = 0.999f * sh_h[b * HID + jbase + j] + 0.001f * act;
            g_h[(s + 1) & 1][(size_t)(b0 + b) * HID + jbase + j] = hn;
        }

        // ---- cluster arrive (release: publishes the g_h stores) ----
        asm volatile("barrier.cluster.arrive.aligned;" ::: "memory");

        // ---- output projection for step s-1 (overlaps barrier wait) ----
        if (s > 0) {
            const float* hr = sh_h + orow_local * HID + oksub * 32;
            const float* wc = sh_wout + oksub * 32 * OUTSZ + oo;
            float oa0 = 0.f, oa1 = 0.f;
#pragma unroll
            for (int k = 0; k < 32; k += 2) {
                oa0 = fmaf(hr[k],     wc[k * OUTSZ],       oa0);
                oa1 = fmaf(hr[k + 1], wc[(k + 1) * OUTSZ], oa1);
            }
            sh_opart[oksub * 64 + orow_el] = oa0 + oa1;
        }
        __syncthreads();
        if (s > 0 && tid < 64) {
            float v = sh_bout[tid & 31];
#pragma unroll
            for (int k = 0; k < NSEG; k++) v += sh_opart[k * 64 + tid];
            int row = b0 + 2 * rank + (tid >> 5);
            out[((size_t)(s - 1) * BATCH + row) * OUTSZ + (tid & 31)] = v;
        }

        // ---- cluster wait (acquire) ----
        asm volatile("barrier.cluster.wait.aligned;" ::: "memory");
    }

    // ---- epilogue: out[1023] from H_1024 (in g_h[0]) ----
    {
        const float4* hs = (const float4*)(g_h[0] + (size_t)b0 * HID);
        sh_h4[tid]        = __ldcv(hs + tid);
        sh_h4[tid + THR2] = __ldcv(hs + tid + THR2);
        __syncthreads();
        {
            const float* hr = sh_h + orow_local * HID + oksub * 32;
            const float* wc = sh_wout + oksub * 32 * OUTSZ + oo;
            float oa0 = 0.f, oa1 = 0.f;
#pragma unroll
            for (int k = 0; k < 32; k += 2) {
                oa0 = fmaf(hr[k],     wc[k * OUTSZ],       oa0);
                oa1 = fmaf(hr[k + 1], wc[(k + 1) * OUTSZ], oa1);
            }
            sh_opart[oksub * 64 + orow_el] = oa0 + oa1;
        }
        __syncthreads();
        if (tid < 64) {
            float v = sh_bout[tid & 31];
#pragma unroll
            for (int k = 0; k < NSEG; k++) v += sh_opart[k * 64 + tid];
            int row = b0 + 2 * rank + (tid >> 5);
            out[((size_t)(TSTEPS - 1) * BATCH + row) * OUTSZ + (tid & 31)] = v;
        }
    }
}

// ---------------------------------------------------------------------------
extern "C" void kernel_launch(void* const* d_in, const int* in_sizes, int n_in,
                              void* d_out, int out_size)
{
    const float* inputs = (const float*)d_in[0];
    const float* Wrec   = (const float*)d_in[1];
    const float* Win    = (const float*)d_in[2];
    const float* brec   = (const float*)d_in[3];
    const float* Wout   = (const float*)d_in[4];
    const float* bout   = (const float*)d_in[5];
    float* out = (float*)d_out;

    const int smem1 = (128 * 132 + 128 * 128) * 4;   // 133120
    cudaFuncSetAttribute(xproj_kernel, cudaFuncAttributeMaxDynamicSharedMemorySize, smem1);
    cudaFuncSetAttribute(rnn_kernel,   cudaFuncAttributeMaxDynamicSharedMemorySize, SM2_BYTES);

    dim3 g1((TSTEPS * BATCH) / 128, HID / 128);
    xproj_kernel<<<g1, 256, smem1>>>(inputs, Win, brec);

    rnn_kernel<<<128, THR2, SM2_BYTES>>>(Wrec, Wout, bout, out);

    (void)in_sizes; (void)n_in; (void)out_size;
}

// round 11
// speedup vs baseline: 1.0657x; 1.0657x over previous
#include <cuda_runtime.h>
#include <cstdint>

#define TSTEPS 1024
#define BATCH  256
#define INSZ   128
#define HID    512
#define OUTSZ  32
#define RB     16      // batch rows per cluster
#define JT     64      // hidden outputs per CTA
#define CLUSZ  8       // CTAs per cluster
#define THR2   1024    // threads per rnn CTA
#define NSEG   16      // k-segments (32 wide each)

// scratch (device globals: the sanctioned no-alloc workaround)
__device__ float g_xproj[(size_t)TSTEPS * BATCH * HID];   // 512 MB
__device__ float g_h[2][BATCH * HID];                     // double-buffered state

// ---------------- packed f32x2 helpers (sm_103a FFMA2) ----------------
__device__ __forceinline__ void fma2(unsigned long long& d,
                                     unsigned long long a,
                                     unsigned long long b) {
    asm("fma.rn.f32x2 %0, %1, %2, %0;" : "+l"(d) : "l"(a), "l"(b));
}
__device__ __forceinline__ unsigned long long splat2(float a) {
    unsigned long long r;
    asm("mov.b64 %0, {%1, %1};" : "=l"(r) : "f"(a));
    return r;
}
__device__ __forceinline__ float2 unpk(unsigned long long v) {
    float2 f;
    asm("mov.b64 {%0, %1}, %2;" : "=f"(f.x), "=f"(f.y) : "l"(v));
    return f;
}
__device__ __forceinline__ uint32_t smem_u32(const void* p) {
    uint32_t a;
    asm("{ .reg .u64 t; cvta.to.shared.u64 t, %1; cvt.u32.u64 %0, t; }"
        : "=r"(a) : "l"(p));
    return a;
}
// 16B async copy, L2-only fill (.cg) — zero register residency
__device__ __forceinline__ void cp16_cg(uint32_t dst_smem, const void* src) {
    asm volatile("cp.async.cg.shared.global [%0], [%1], 16;"
                 :: "r"(dst_smem), "l"(src) : "memory");
}
__device__ __forceinline__ void cp_commit() {
    asm volatile("cp.async.commit_group;" ::: "memory");
}
__device__ __forceinline__ void cp_wait_all() {
    asm volatile("cp.async.wait_group 0;" ::: "memory");
}

// ---------------------------------------------------------------------------
// Kernel 1: x_proj[t,b,:] = inputs[t,b,:] @ W_in + b_rec   (M=262144,K=128,N=512)
// ---------------------------------------------------------------------------
__global__ void __launch_bounds__(256, 1)
xproj_kernel(const float* __restrict__ in, const float* __restrict__ Win,
             const float* __restrict__ brec)
{
    extern __shared__ float sm1[];
    float*  As  = sm1;               // [128][132] padded
    float4* As4 = (float4*)As;
    float*  Bs  = sm1 + 128 * 132;   // [128][128]
    float4* Bs4 = (float4*)Bs;

    const int tid = threadIdx.x;
    const int m0  = blockIdx.x * 128;
    const int n0  = blockIdx.y * 128;

    for (int i = tid; i < 4096; i += 256) {
        int m = i >> 5, kq = i & 31;
        As4[m * 33 + kq] = *(const float4*)(in + (size_t)(m0 + m) * INSZ + kq * 4);
    }
    for (int i = tid; i < 4096; i += 256) {
        int k = i >> 5, nq = i & 31;
        Bs4[k * 32 + nq] = *(const float4*)(Win + (size_t)k * HID + n0 + nq * 4);
    }
    __syncthreads();

    const int tx = tid & 15, ty = tid >> 4;
    const int mm = ty * 8,   nn = tx * 8;

    unsigned long long accq[8][4];
#pragma unroll
    for (int i = 0; i < 8; i++)
#pragma unroll
        for (int jj = 0; jj < 4; jj++) accq[i][jj] = 0ULL;

#pragma unroll 4
    for (int k = 0; k < 128; k++) {
        unsigned long long aa[8];
#pragma unroll
        for (int i = 0; i < 8; i++) aa[i] = splat2(As[(mm + i) * 132 + k]);
        const ulonglong2* bq = (const ulonglong2*)(Bs4 + k * 32 + (nn >> 2));
        ulonglong2 bA = bq[0];
        ulonglong2 bB = bq[1];
#pragma unroll
        for (int i = 0; i < 8; i++) {
            fma2(accq[i][0], aa[i], bA.x);
            fma2(accq[i][1], aa[i], bA.y);
            fma2(accq[i][2], aa[i], bB.x);
            fma2(accq[i][3], aa[i], bB.y);
        }
    }

    float4 br0 = *(const float4*)(brec + n0 + nn);
    float4 br1 = *(const float4*)(brec + n0 + nn + 4);
#pragma unroll
    for (int i = 0; i < 8; i++) {
        float2 p0 = unpk(accq[i][0]), p1 = unpk(accq[i][1]);
        float2 p2 = unpk(accq[i][2]), p3 = unpk(accq[i][3]);
        float4 s0 = make_float4(p0.x + br0.x, p0.y + br0.y, p1.x + br0.z, p1.y + br0.w);
        float4 s1 = make_float4(p2.x + br1.x, p2.y + br1.y, p3.x + br1.z, p3.y + br1.w);
        float* dst = g_xproj + (size_t)(m0 + mm + i) * HID + n0 + nn;
        *(float4*)dst       = s0;
        *(float4*)(dst + 4) = s1;
    }
}

// ---------------------------------------------------------------------------
// Kernel 2: persistent recurrence + fused output projection, 1024 threads/CTA.
// grid = 128 CTAs = 16 clusters x 8; cluster c owns batch rows [16c, 16c+16);
// CTA rank r owns hidden slice [64r, 64r+64). Thread (j = tid&63,
// kseg = tid>>6) holds W_rec[jbase+j][kseg*32 .. +32) in 32 regs.
// xp is prefetched via cp.async.cg into a double-buffered smem tile (no regs).
// ---------------------------------------------------------------------------
// smem layout (floats)
#define SM2_H     0                        // [16][512]            8192
#define SM2_PART  (16 * 512)               // [16][16][64]        16384
#define SM2_OPART (SM2_PART + 16384)       // [16][64]             1024
#define SM2_XP    (SM2_OPART + 1024)       // [2][16][64]          2048
#define SM2_WOUT  (SM2_XP + 2048)          // [512][32]           16384
#define SM2_BOUT  (SM2_WOUT + 16384)       // [32]
#define SM2_BYTES ((SM2_BOUT + 32) * 4)    // ~176 KB

__global__ void __cluster_dims__(CLUSZ, 1, 1) __launch_bounds__(THR2, 1)
rnn_kernel(const float* __restrict__ Wrec, const float* __restrict__ Wout,
           const float* __restrict__ bout, float* __restrict__ out)
{
    extern __shared__ float sm[];
    float*  sh_h     = sm + SM2_H;
    float4* sh_h4    = (float4*)sh_h;
    float*  sh_part  = sm + SM2_PART;
    float*  sh_opart = sm + SM2_OPART;
    float*  sh_xp    = sm + SM2_XP;      // two buffers of 1024 floats
    float*  sh_wout  = sm + SM2_WOUT;
    float*  sh_bout  = sm + SM2_BOUT;

    const int tid   = threadIdx.x;
    const int rank  = blockIdx.x & (CLUSZ - 1);
    const int clu   = blockIdx.x >> 3;
    const int b0    = clu * RB;
    const int jbase = rank * JT;

    const int j    = tid & 63;
    const int kseg = tid >> 6;           // 16 k-segments of 32

    // resident W_rec slice: 32 floats = 8 ulonglong2 = 32 regs
    ulonglong2 W2[8];
    {
        const ulonglong2* wr =
            (const ulonglong2*)(Wrec + (size_t)(jbase + j) * HID + kseg * 32);
#pragma unroll
        for (int q = 0; q < 8; q++) W2[q] = wr[q];
    }
    // W_out / b_out to smem (consumed from s=1 on; first syncthreads covers it)
    {
        const float4* wg = (const float4*)Wout;
        float4* ws = (float4*)sh_wout;
        for (int i = tid; i < HID * OUTSZ / 4; i += THR2) ws[i] = wg[i];
        if (tid < OUTSZ) sh_bout[tid] = bout[tid];
    }

    // xp prefetch geometry: 256 threads each copy one float4 of the [16][64] tile
    const int xb = tid >> 4, xq = tid & 15;
    const float* xsrc0 = g_xproj + (size_t)(b0 + xb) * HID + jbase + xq * 4;
    const uint32_t xp_smem0 = smem_u32(sh_xp) + (uint32_t)(xb * 64 + xq * 4) * 4;

    // prefetch xp for step 0 into buffer 0
    if (tid < 256) cp16_cg(xp_smem0, xsrc0);
    cp_commit();

    for (int s = 0; s < TSTEPS; ++s) {
        // ---- load H_s (full 16x512 = 2048 float4; 2 per thread) ----
        if (s == 0) {
            float4 z = make_float4(0.f, 0.f, 0.f, 0.f);
            sh_h4[tid]        = z;
            sh_h4[tid + THR2] = z;
        } else {
            const float4* hs = (const float4*)(g_h[s & 1] + (size_t)b0 * HID);
            sh_h4[tid]        = __ldcv(hs + tid);
            sh_h4[tid + THR2] = __ldcv(hs + tid + THR2);
        }
        cp_wait_all();          // xp(s) landed in buffer s&1
        __syncthreads();

        // prefetch xp(s+1) into the other buffer (hidden under the matmul)
        if (s + 1 < TSTEPS && tid < 256)
            cp16_cg(xp_smem0 + ((s + 1) & 1) * 4096,
                    xsrc0 + (size_t)(s + 1) * BATCH * HID);
        cp_commit();

        const float* xp_cur = sh_xp + (s & 1) * 1024;

        // ---- recurrent matmul partials: pre[b][j] over this 32-wide k-segment ----
        {
            const float* hbase = sh_h + kseg * 32;
#pragma unroll 1
            for (int b = 0; b < RB; b++) {
                const ulonglong2* hrow = (const ulonglong2*)(hbase + b * HID);
                unsigned long long a01 = 0ULL, a23 = 0ULL;
#pragma unroll
                for (int q = 0; q < 8; q++) {
                    ulonglong2 hv = hrow[q];
                    fma2(a01, W2[q].x, hv.x);
                    fma2(a23, W2[q].y, hv.y);
                }
                float2 u = unpk(a01), v = unpk(a23);
                sh_part[(b * NSEG + kseg) * 64 + j] = (u.x + u.y) + (v.x + v.y);
            }
        }
        __syncthreads();

        // ---- state update: H_{s+1}, one (b,j) element per thread ----
        {
            const int b = tid >> 6;          // j = tid & 63
            float pre = 0.f;
#pragma unroll
            for (int k = 0; k < NSEG; k++)
                pre += sh_part[(b * NSEG + k) * 64 + j];
            float act = pre + xp_cur[b * 64 + j];
            act = act > 0.f ? act : 0.f;
            float hn = 0.999f * sh_h[b * HID + jbase + j] + 0.001f * act;
            g_h[(s + 1) & 1][(size_t)(b0 + b) * HID + jbase + j] = hn;
        }

        // ---- cluster arrive (release: publishes the g_h stores) ----
        asm volatile("barrier.cluster.arrive.aligned;" ::: "memory");

        // ---- output projection for step s-1 (overlaps barrier wait) ----
        if (s > 0) {
            const int oo   = tid & 31;
            const int orow = 2 * rank + ((tid >> 5) & 1);
            const int oks  = tid >> 6;
            const float* hr = sh_h + orow * HID + oks * 32;
            const float* wc = sh_wout + oks * 32 * OUTSZ + oo;
            float oa0 = 0.f, oa1 = 0.f;
#pragma unroll
            for (int k = 0; k < 32; k += 2) {
                oa0 = fmaf(hr[k],     wc[k * OUTSZ],       oa0);
                oa1 = fmaf(hr[k + 1], wc[(k + 1) * OUTSZ], oa1);
            }
            sh_opart[oks * 64 + (tid & 63)] = oa0 + oa1;
        }
        __syncthreads();
        if (s > 0 && tid < 64) {
            float v = sh_bout[tid & 31];
#pragma unroll
            for (int k = 0; k < NSEG; k++) v += sh_opart[k * 64 + tid];
            int row = b0 + 2 * rank + (tid >> 5);
            out[((size_t)(s - 1) * BATCH + row) * OUTSZ + (tid & 31)] = v;
        }

        // ---- cluster wait (acquire) ----
        asm volatile("barrier.cluster.wait.aligned;" ::: "memory");
    }

    // ---- epilogue: out[1023] from H_1024 (in g_h[0]) ----
    {
        const float4* hs = (const float4*)(g_h[0] + (size_t)b0 * HID);
        sh_h4[tid]        = __ldcv(hs + tid);
        sh_h4[tid + THR2] = __ldcv(hs + tid + THR2);
        __syncthreads();
        {
            const int oo   = tid & 31;
            const int orow = 2 * rank + ((tid >> 5) & 1);
            const int oks  = tid >> 6;
            const float* hr = sh_h + orow * HID + oks * 32;
            const float* wc = sh_wout + oks * 32 * OUTSZ + oo;
            float oa0 = 0.f, oa1 = 0.f;
#pragma unroll
            for (int k = 0; k < 32; k += 2) {
                oa0 = fmaf(hr[k],     wc[k * OUTSZ],       oa0);
                oa1 = fmaf(hr[k + 1], wc[(k + 1) * OUTSZ], oa1);
            }
            sh_opart[oks * 64 + (tid & 63)] = oa0 + oa1;
        }
        __syncthreads();
        if (tid < 64) {
            float v = sh_bout[tid & 31];
#pragma unroll
            for (int k = 0; k < NSEG; k++) v += sh_opart[k * 64 + tid];
            int row = b0 + 2 * rank + (tid >> 5);
            out[((size_t)(TSTEPS - 1) * BATCH + row) * OUTSZ + (tid & 31)] = v;
        }
    }
}

// ---------------------------------------------------------------------------
extern "C" void kernel_launch(void* const* d_in, const int* in_sizes, int n_in,
                              void* d_out, int out_size)
{
    const float* inputs = (const float*)d_in[0];
    const float* Wrec   = (const float*)d_in[1];
    const float* Win    = (const float*)d_in[2];
    const float* brec   = (const float*)d_in[3];
    const float* Wout   = (const float*)d_in[4];
    const float* bout   = (const float*)d_in[5];
    float* out = (float*)d_out;

    const int smem1 = (128 * 132 + 128 * 128) * 4;   // 133120
    cudaFuncSetAttribute(xproj_kernel, cudaFuncAttributeMaxDynamicSharedMemorySize, smem1);
    cudaFuncSetAttribute(rnn_kernel,   cudaFuncAttributeMaxDynamicSharedMemorySize, SM2_BYTES);

    dim3 g1((TSTEPS * BATCH) / 128, HID / 128);
    xproj_kernel<<<g1, 256, smem1>>>(inputs, Win, brec);

    rnn_kernel<<<128, THR2, SM2_BYTES>>>(Wrec, Wout, bout, out);

    (void)in_sizes; (void)n_in; (void)out_size;
}

// round 12
// speedup vs baseline: 1.2541x; 1.1768x over previous
#include <cuda_runtime.h>
#include <cstdint>

#define TSTEPS 1024
#define BATCH  256
#define INSZ   128
#define HID    512
#define OUTSZ  32
#define RB     16      // batch rows per cluster
#define JT     64      // hidden outputs per CTA
#define CLUSZ  8       // CTAs per cluster
#define THR2   512     // threads per rnn CTA
#define NSEG   16      // k-segments (32 wide each)

// scratch (device globals: the sanctioned no-alloc workaround)
__device__ float g_xproj[(size_t)TSTEPS * BATCH * HID];   // 512 MB
__device__ float g_h[2][BATCH * HID];                     // double-buffered state

// ---------------- packed f32x2 helpers (sm_103a FFMA2) ----------------
__device__ __forceinline__ void fma2(unsigned long long& d,
                                     unsigned long long a,
                                     unsigned long long b) {
    asm("fma.rn.f32x2 %0, %1, %2, %0;" : "+l"(d) : "l"(a), "l"(b));
}
__device__ __forceinline__ unsigned long long splat2(float a) {
    unsigned long long r;
    asm("mov.b64 %0, {%1, %1};" : "=l"(r) : "f"(a));
    return r;
}
__device__ __forceinline__ float2 unpk(unsigned long long v) {
    float2 f;
    asm("mov.b64 {%0, %1}, %2;" : "=f"(f.x), "=f"(f.y) : "l"(v));
    return f;
}
__device__ __forceinline__ uint32_t smem_u32(const void* p) {
    uint32_t a;
    asm("{ .reg .u64 t; cvta.to.shared.u64 t, %1; cvt.u32.u64 %0, t; }"
        : "=r"(a) : "l"(p));
    return a;
}
// 16B async copy, L2-only fill (.cg) — zero register residency
__device__ __forceinline__ void cp16_cg(uint32_t dst_smem, const void* src) {
    asm volatile("cp.async.cg.shared.global [%0], [%1], 16;"
                 :: "r"(dst_smem), "l"(src) : "memory");
}
__device__ __forceinline__ void cp_commit() {
    asm volatile("cp.async.commit_group;" ::: "memory");
}
__device__ __forceinline__ void cp_wait_all() {
    asm volatile("cp.async.wait_group 0;" ::: "memory");
}

// ---------------------------------------------------------------------------
// Kernel 1: x_proj[t,b,:] = inputs[t,b,:] @ W_in + b_rec   (M=262144,K=128,N=512)
// ---------------------------------------------------------------------------
__global__ void __launch_bounds__(256, 1)
xproj_kernel(const float* __restrict__ in, const float* __restrict__ Win,
             const float* __restrict__ brec)
{
    extern __shared__ float sm1[];
    float*  As  = sm1;               // [128][132] padded
    float4* As4 = (float4*)As;
    float*  Bs  = sm1 + 128 * 132;   // [128][128]
    float4* Bs4 = (float4*)Bs;

    const int tid = threadIdx.x;
    const int m0  = blockIdx.x * 128;
    const int n0  = blockIdx.y * 128;

    for (int i = tid; i < 4096; i += 256) {
        int m = i >> 5, kq = i & 31;
        As4[m * 33 + kq] = *(const float4*)(in + (size_t)(m0 + m) * INSZ + kq * 4);
    }
    for (int i = tid; i < 4096; i += 256) {
        int k = i >> 5, nq = i & 31;
        Bs4[k * 32 + nq] = *(const float4*)(Win + (size_t)k * HID + n0 + nq * 4);
    }
    __syncthreads();

    const int tx = tid & 15, ty = tid >> 4;
    const int mm = ty * 8,   nn = tx * 8;

    unsigned long long accq[8][4];
#pragma unroll
    for (int i = 0; i < 8; i++)
#pragma unroll
        for (int jj = 0; jj < 4; jj++) accq[i][jj] = 0ULL;

#pragma unroll 4
    for (int k = 0; k < 128; k++) {
        unsigned long long aa[8];
#pragma unroll
        for (int i = 0; i < 8; i++) aa[i] = splat2(As[(mm + i) * 132 + k]);
        const ulonglong2* bq = (const ulonglong2*)(Bs4 + k * 32 + (nn >> 2));
        ulonglong2 bA = bq[0];
        ulonglong2 bB = bq[1];
#pragma unroll
        for (int i = 0; i < 8; i++) {
            fma2(accq[i][0], aa[i], bA.x);
            fma2(accq[i][1], aa[i], bA.y);
            fma2(accq[i][2], aa[i], bB.x);
            fma2(accq[i][3], aa[i], bB.y);
        }
    }

    float4 br0 = *(const float4*)(brec + n0 + nn);
    float4 br1 = *(const float4*)(brec + n0 + nn + 4);
#pragma unroll
    for (int i = 0; i < 8; i++) {
        float2 p0 = unpk(accq[i][0]), p1 = unpk(accq[i][1]);
        float2 p2 = unpk(accq[i][2]), p3 = unpk(accq[i][3]);
        float4 s0 = make_float4(p0.x + br0.x, p0.y + br0.y, p1.x + br0.z, p1.y + br0.w);
        float4 s1 = make_float4(p2.x + br1.x, p2.y + br1.y, p3.x + br1.z, p3.y + br1.w);
        float* dst = g_xproj + (size_t)(m0 + mm + i) * HID + n0 + nn;
        *(float4*)dst       = s0;
        *(float4*)(dst + 4) = s1;
    }
}

// ---------------------------------------------------------------------------
// Kernel 2: persistent recurrence + fused output projection, 512 threads/CTA.
// grid = 128 CTAs = 16 clusters x 8; cluster c owns batch rows [16c, 16c+16);
// CTA rank r owns hidden slice [64r, 64r+64).
// Thread (j2 = tid&31, kseg = tid>>5 in [0,16)) owns TWO W_rec rows
// (jbase+j2 and jbase+j2+32) over k in [kseg*32, kseg*32+32): 64 W regs,
// and each h element loaded from smem feeds 2 FFMA2 (halves LDS traffic).
// 2 syncthreads/step + 1 cluster barrier; oproj rides inside existing phases.
// ---------------------------------------------------------------------------
// smem layout (floats)
#define SM2_H     0                        // [16][512]            8192
#define SM2_PART  (16 * 512)               // [16][16][64]        16384
#define SM2_OPART (SM2_PART + 16384)       // [8][64]               512
#define SM2_XP    (SM2_OPART + 512)        // [2][16][64]          2048
#define SM2_WOUT  (SM2_XP + 2048)          // [512][32]           16384
#define SM2_BOUT  (SM2_WOUT + 16384)       // [32]
#define SM2_BYTES ((SM2_BOUT + 32) * 4)

__global__ void __cluster_dims__(CLUSZ, 1, 1) __launch_bounds__(THR2, 1)
rnn_kernel(const float* __restrict__ Wrec, const float* __restrict__ Wout,
           const float* __restrict__ bout, float* __restrict__ out)
{
    extern __shared__ float sm[];
    float*  sh_h     = sm + SM2_H;
    float4* sh_h4    = (float4*)sh_h;
    float*  sh_part  = sm + SM2_PART;
    float*  sh_opart = sm + SM2_OPART;
    float*  sh_xp    = sm + SM2_XP;      // two buffers of 1024 floats
    float*  sh_wout  = sm + SM2_WOUT;
    float*  sh_bout  = sm + SM2_BOUT;

    const int tid   = threadIdx.x;
    const int rank  = blockIdx.x & (CLUSZ - 1);
    const int clu   = blockIdx.x >> 3;
    const int b0    = clu * RB;
    const int jbase = rank * JT;

    const int j2   = tid & 31;
    const int kseg = tid >> 5;           // 16 k-segments of 32

    // resident W_rec: rows jbase+j2 and jbase+j2+32, k in [kseg*32, +32)
    ulonglong2 WA[8], WB[8];
    {
        const ulonglong2* wra =
            (const ulonglong2*)(Wrec + (size_t)(jbase + j2) * HID + kseg * 32);
        const ulonglong2* wrb =
            (const ulonglong2*)(Wrec + (size_t)(jbase + j2 + 32) * HID + kseg * 32);
#pragma unroll
        for (int q = 0; q < 8; q++) { WA[q] = wra[q]; WB[q] = wrb[q]; }
    }
    // W_out / b_out to smem (consumed from s=1 on; first syncthreads covers it)
    {
        const float4* wg = (const float4*)Wout;
        float4* ws = (float4*)sh_wout;
        for (int i = tid; i < HID * OUTSZ / 4; i += THR2) ws[i] = wg[i];
        if (tid < OUTSZ) sh_bout[tid] = bout[tid];
    }

    // xp prefetch geometry: 256 threads each copy one float4 of the [16][64] tile
    const int xb = tid >> 4, xq = tid & 15;
    const float* xsrc0 = g_xproj + (size_t)(b0 + xb) * HID + jbase + xq * 4;
    const uint32_t xp_smem0 = smem_u32(sh_xp) + (uint32_t)(xb * 64 + xq * 4) * 4;

    // prefetch xp for step 0 into buffer 0
    if (tid < 256) cp16_cg(xp_smem0, xsrc0);
    cp_commit();

    // oproj mapping: oo = out col, orow = 1 of 2 rows for this rank, oks = k-chunk/8
    const int oo   = tid & 31;
    const int orow = 2 * rank + ((tid >> 5) & 1);
    const int oks  = tid >> 6;           // 8 chunks of 64

    for (int s = 0; s < TSTEPS; ++s) {
        // ---- load H_s (full 16x512 = 2048 float4; 4 per thread) ----
        if (s == 0) {
            float4 z = make_float4(0.f, 0.f, 0.f, 0.f);
#pragma unroll
            for (int u = 0; u < 4; u++) sh_h4[tid + THR2 * u] = z;
        } else {
            const float4* hs = (const float4*)(g_h[s & 1] + (size_t)b0 * HID);
#pragma unroll
            for (int u = 0; u < 4; u++)
                sh_h4[tid + THR2 * u] = __ldcv(hs + tid + THR2 * u);
        }
        cp_wait_all();          // xp(s) landed in buffer s&1
        __syncthreads();        // sync1: sh_h + xp ready

        // prefetch xp(s+1) into the other buffer (hidden under the matmul)
        if (s + 1 < TSTEPS && tid < 256)
            cp16_cg(xp_smem0 + ((s + 1) & 1) * 4096,
                    xsrc0 + (size_t)(s + 1) * BATCH * HID);
        cp_commit();

        // ---- output projection (accumulate) for step s-1: reads sh_h only ----
        if (s > 0) {
            const float* hr = sh_h + orow * HID + oks * 64;
            const float* wc = sh_wout + oks * 64 * OUTSZ + oo;
            float oa0 = 0.f, oa1 = 0.f;
#pragma unroll 8
            for (int k = 0; k < 64; k += 2) {
                oa0 = fmaf(hr[k],     wc[k * OUTSZ],       oa0);
                oa1 = fmaf(hr[k + 1], wc[(k + 1) * OUTSZ], oa1);
            }
            sh_opart[oks * 64 + (tid & 63)] = oa0 + oa1;
        }

        // ---- recurrent matmul partials: two j-rows per thread, 32-wide k ----
        {
            const float* hbase = sh_h + kseg * 32;
#pragma unroll 2
            for (int b = 0; b < RB; b++) {
                const ulonglong2* hrow = (const ulonglong2*)(hbase + b * HID);
                unsigned long long aA0 = 0ULL, aA1 = 0ULL;
                unsigned long long aB0 = 0ULL, aB1 = 0ULL;
#pragma unroll
                for (int q = 0; q < 8; q++) {
                    ulonglong2 hv = hrow[q];
                    fma2(aA0, WA[q].x, hv.x);
                    fma2(aA1, WA[q].y, hv.y);
                    fma2(aB0, WB[q].x, hv.x);
                    fma2(aB1, WB[q].y, hv.y);
                }
                float2 uA = unpk(aA0), vA = unpk(aA1);
                float2 uB = unpk(aB0), vB = unpk(aB1);
                float* pp = sh_part + (b * NSEG + kseg) * 64;
                pp[j2]      = (uA.x + uA.y) + (vA.x + vA.y);
                pp[j2 + 32] = (uB.x + uB.y) + (vB.x + vB.y);
            }
        }
        __syncthreads();        // sync2: sh_part + sh_opart ready

        // ---- state update: H_{s+1}, two (b,j) elements per thread ----
        {
            const float* xp_cur = sh_xp + (s & 1) * 1024;
            float* gdst = g_h[(s + 1) & 1];
#pragma unroll
            for (int u = 0; u < 2; u++) {
                const int idx = tid + THR2 * u;
                const int b = idx >> 6, j = idx & 63;
                float pre = 0.f;
#pragma unroll
                for (int k = 0; k < NSEG; k++)
                    pre += sh_part[(b * NSEG + k) * 64 + j];
                float act = pre + xp_cur[b * 64 + j];
                act = act > 0.f ? act : 0.f;
                float hn = 0.999f * sh_h[b * HID + jbase + j] + 0.001f * act;
                gdst[(size_t)(b0 + b) * HID + jbase + j] = hn;
            }
        }
        // ---- output projection (finalize) for step s-1 ----
        if (s > 0 && tid < 64) {
            float v = sh_bout[tid & 31];
#pragma unroll
            for (int k = 0; k < 8; k++) v += sh_opart[k * 64 + tid];
            int row = b0 + 2 * rank + (tid >> 5);
            out[((size_t)(s - 1) * BATCH + row) * OUTSZ + (tid & 31)] = v;
        }

        // cluster barrier: release publishes g_h stores; also orders CTA-local
        // sh_h reuse (all threads must arrive before any proceeds).
        asm volatile("barrier.cluster.arrive.aligned;" ::: "memory");
        asm volatile("barrier.cluster.wait.aligned;"   ::: "memory");
    }

    // ---- epilogue: out[1023] from H_1024 (in g_h[0]) ----
    {
        const float4* hs = (const float4*)(g_h[0] + (size_t)b0 * HID);
#pragma unroll
        for (int u = 0; u < 4; u++)
            sh_h4[tid + THR2 * u] = __ldcv(hs + tid + THR2 * u);
        __syncthreads();
        {
            const float* hr = sh_h + orow * HID + oks * 64;
            const float* wc = sh_wout + oks * 64 * OUTSZ + oo;
            float oa0 = 0.f, oa1 = 0.f;
#pragma unroll 8
            for (int k = 0; k < 64; k += 2) {
                oa0 = fmaf(hr[k],     wc[k * OUTSZ],       oa0);
                oa1 = fmaf(hr[k + 1], wc[(k + 1) * OUTSZ], oa1);
            }
            sh_opart[oks * 64 + (tid & 63)] = oa0 + oa1;
        }
        __syncthreads();
        if (tid < 64) {
            float v = sh_bout[tid & 31];
#pragma unroll
            for (int k = 0; k < 8; k++) v += sh_opart[k * 64 + tid];
            int row = b0 + 2 * rank + (tid >> 5);
            out[((size_t)(TSTEPS - 1) * BATCH + row) * OUTSZ + (tid & 31)] = v;
        }
    }
}

// ---------------------------------------------------------------------------
extern "C" void kernel_launch(void* const* d_in, const int* in_sizes, int n_in,
                              void* d_out, int out_size)
{
    const float* inputs = (const float*)d_in[0];
    const float* Wrec   = (const float*)d_in[1];
    const float* Win    = (const float*)d_in[2];
    const float* brec   = (const float*)d_in[3];
    const float* Wout   = (const float*)d_in[4];
    const float* bout   = (const float*)d_in[5];
    float* out = (float*)d_out;

    const int smem1 = (128 * 132 + 128 * 128) * 4;   // 133120
    cudaFuncSetAttribute(xproj_kernel, cudaFuncAttributeMaxDynamicSharedMemorySize, smem1);
    cudaFuncSetAttribute(rnn_kernel,   cudaFuncAttributeMaxDynamicSharedMemorySize, SM2_BYTES);

    dim3 g1((TSTEPS * BATCH) / 128, HID / 128);
    xproj_kernel<<<g1, 256, smem1>>>(inputs, Win, brec);

    rnn_kernel<<<128, THR2, SM2_BYTES>>>(Wrec, Wout, bout, out);

    (void)in_sizes; (void)n_in; (void)out_size;
}

// round 13
// speedup vs baseline: 1.7968x; 1.4328x over previous
#include <cuda_runtime.h>
#include <cstdint>

#define TSTEPS 1024
#define BATCH  256
#define INSZ   128
#define HID    512
#define OUTSZ  32
#define RB     16      // batch rows per cluster
#define JT     64      // hidden outputs per CTA
#define CLUSZ  8       // CTAs per cluster
#define THR2   1024    // threads per rnn CTA (32 warps)
#define HPAD   516     // padded h row (conflict-free tf32 A-frag loads)

// scratch (device globals: the sanctioned no-alloc workaround)
__device__ float g_xproj[(size_t)TSTEPS * BATCH * HID];   // 512 MB
__device__ float g_h[2][BATCH * HID];                     // double-buffered state

// ---------------- packed f32x2 helpers (xproj kernel) ----------------
__device__ __forceinline__ void fma2(unsigned long long& d,
                                     unsigned long long a,
                                     unsigned long long b) {
    asm("fma.rn.f32x2 %0, %1, %2, %0;" : "+l"(d) : "l"(a), "l"(b));
}
__device__ __forceinline__ unsigned long long splat2(float a) {
    unsigned long long r;
    asm("mov.b64 %0, {%1, %1};" : "=l"(r) : "f"(a));
    return r;
}
__device__ __forceinline__ float2 unpk(unsigned long long v) {
    float2 f;
    asm("mov.b64 {%0, %1}, %2;" : "=f"(f.x), "=f"(f.y) : "l"(v));
    return f;
}
__device__ __forceinline__ uint32_t smem_u32(const void* p) {
    uint32_t a;
    asm("{ .reg .u64 t; cvta.to.shared.u64 t, %1; cvt.u32.u64 %0, t; }"
        : "=r"(a) : "l"(p));
    return a;
}
__device__ __forceinline__ void cp16_cg(uint32_t dst_smem, const void* src) {
    asm volatile("cp.async.cg.shared.global [%0], [%1], 16;"
                 :: "r"(dst_smem), "l"(src) : "memory");
}
__device__ __forceinline__ void cp_commit() {
    asm volatile("cp.async.commit_group;" ::: "memory");
}
__device__ __forceinline__ void cp_wait_all() {
    asm volatile("cp.async.wait_group 0;" ::: "memory");
}
// ---------------- tf32 mma helpers ----------------
__device__ __forceinline__ uint32_t to_tf32(float f) {
    uint32_t u;
    asm("cvt.rna.tf32.f32 %0, %1;" : "=r"(u) : "f"(f));
    return u;
}
__device__ __forceinline__ void mma_tf32(float& c0, float& c1, float& c2, float& c3,
                                         uint32_t a0, uint32_t a1, uint32_t a2, uint32_t a3,
                                         uint32_t b0, uint32_t b1) {
    asm volatile("mma.sync.aligned.m16n8k8.row.col.f32.tf32.tf32.f32 "
                 "{%0,%1,%2,%3}, {%4,%5,%6,%7}, {%8,%9}, {%0,%1,%2,%3};"
                 : "+f"(c0), "+f"(c1), "+f"(c2), "+f"(c3)
                 : "r"(a0), "r"(a1), "r"(a2), "r"(a3), "r"(b0), "r"(b1));
}

// ---------------------------------------------------------------------------
// Kernel 1: x_proj[t,b,:] = inputs[t,b,:] @ W_in + b_rec   (M=262144,K=128,N=512)
// ---------------------------------------------------------------------------
__global__ void __launch_bounds__(256, 1)
xproj_kernel(const float* __restrict__ in, const float* __restrict__ Win,
             const float* __restrict__ brec)
{
    extern __shared__ float sm1[];
    float*  As  = sm1;               // [128][132] padded
    float4* As4 = (float4*)As;
    float*  Bs  = sm1 + 128 * 132;   // [128][128]
    float4* Bs4 = (float4*)Bs;

    const int tid = threadIdx.x;
    const int m0  = blockIdx.x * 128;
    const int n0  = blockIdx.y * 128;

    for (int i = tid; i < 4096; i += 256) {
        int m = i >> 5, kq = i & 31;
        As4[m * 33 + kq] = *(const float4*)(in + (size_t)(m0 + m) * INSZ + kq * 4);
    }
    for (int i = tid; i < 4096; i += 256) {
        int k = i >> 5, nq = i & 31;
        Bs4[k * 32 + nq] = *(const float4*)(Win + (size_t)k * HID + n0 + nq * 4);
    }
    __syncthreads();

    const int tx = tid & 15, ty = tid >> 4;
    const int mm = ty * 8,   nn = tx * 8;

    unsigned long long accq[8][4];
#pragma unroll
    for (int i = 0; i < 8; i++)
#pragma unroll
        for (int jj = 0; jj < 4; jj++) accq[i][jj] = 0ULL;

#pragma unroll 4
    for (int k = 0; k < 128; k++) {
        unsigned long long aa[8];
#pragma unroll
        for (int i = 0; i < 8; i++) aa[i] = splat2(As[(mm + i) * 132 + k]);
        const ulonglong2* bq = (const ulonglong2*)(Bs4 + k * 32 + (nn >> 2));
        ulonglong2 bA = bq[0];
        ulonglong2 bB = bq[1];
#pragma unroll
        for (int i = 0; i < 8; i++) {
            fma2(accq[i][0], aa[i], bA.x);
            fma2(accq[i][1], aa[i], bA.y);
            fma2(accq[i][2], aa[i], bB.x);
            fma2(accq[i][3], aa[i], bB.y);
        }
    }

    float4 br0 = *(const float4*)(brec + n0 + nn);
    float4 br1 = *(const float4*)(brec + n0 + nn + 4);
#pragma unroll
    for (int i = 0; i < 8; i++) {
        float2 p0 = unpk(accq[i][0]), p1 = unpk(accq[i][1]);
        float2 p2 = unpk(accq[i][2]), p3 = unpk(accq[i][3]);
        float4 s0 = make_float4(p0.x + br0.x, p0.y + br0.y, p1.x + br0.z, p1.y + br0.w);
        float4 s1 = make_float4(p2.x + br1.x, p2.y + br1.y, p3.x + br1.z, p3.y + br1.w);
        float* dst = g_xproj + (size_t)(m0 + mm + i) * HID + n0 + nn;
        *(float4*)dst       = s0;
        *(float4*)(dst + 4) = s1;
    }
}

// ---------------------------------------------------------------------------
// Kernel 2: persistent recurrence, tf32 mma.sync, 1024 threads/CTA.
// grid = 128 CTAs = 16 clusters x 8; cluster c owns batch rows [16c, 16c+16);
// CTA rank r owns hidden slice [64r, 64r+64).
// Warp w = (noct = w&7, kq = w>>3): computes D[16b x 8j] over k in
// [kq*128, +128) via 16 chained m16n8k8 tf32 MMAs; W^T fragments live in
// 32 regs (cvt.rna once at init). Partials reduced across the 4 kq groups.
// ---------------------------------------------------------------------------
// smem layout (floats)
#define SM2_H     0                         // [16][516]            8256
#define SM2_PART  8256                      // [4][16][64]          4096
#define SM2_OPART (SM2_PART + 4096)         // [16][64]             1024
#define SM2_XP    (SM2_OPART + 1024)        // [2][16][64]          2048
#define SM2_WOUT  (SM2_XP + 2048)           // [512][32]           16384
#define SM2_BOUT  (SM2_WOUT + 16384)        // [32]
#define SM2_BYTES ((SM2_BOUT + 32) * 4)     // 127360 bytes

__global__ void __cluster_dims__(CLUSZ, 1, 1) __launch_bounds__(THR2, 1)
rnn_kernel(const float* __restrict__ Wrec, const float* __restrict__ Wout,
           const float* __restrict__ bout, float* __restrict__ out)
{
    extern __shared__ float sm[];
    float*  sh_h     = sm + SM2_H;       // [16][HPAD]
    float4* sh_h4    = (float4*)sh_h;    // row = 129 float4
    float*  sh_part  = sm + SM2_PART;
    float*  sh_opart = sm + SM2_OPART;
    float*  sh_xp    = sm + SM2_XP;
    float*  sh_wout  = sm + SM2_WOUT;
    float*  sh_bout  = sm + SM2_BOUT;

    const int tid   = threadIdx.x;
    const int lane  = tid & 31;
    const int warp  = tid >> 5;          // 0..31
    const int noct  = warp & 7;          // j-octet within JT
    const int kq    = warp >> 3;         // k-quarter (128 wide)
    const int rank  = blockIdx.x & (CLUSZ - 1);
    const int clu   = blockIdx.x >> 3;
    const int b0    = clu * RB;
    const int jbase = rank * JT;

    // ---- B fragments: W^T for this warp's (noct, kq), tf32, resident ----
    // B[k][n] = W_rec[jbase + noct*8 + n][k];  b0: k=lane%4, n=lane/4; b1: k+4
    uint32_t Bf[16][2];
    {
        const int n  = lane >> 2;
        const int kk0 = lane & 3;
        const float* wr = Wrec + (size_t)(jbase + noct * 8 + n) * HID + kq * 128 + kk0;
#pragma unroll
        for (int kk = 0; kk < 16; kk++) {
            Bf[kk][0] = to_tf32(wr[kk * 8]);
            Bf[kk][1] = to_tf32(wr[kk * 8 + 4]);
        }
    }
    // W_out / b_out to smem
    {
        const float4* wg = (const float4*)Wout;
        float4* ws = (float4*)sh_wout;
        for (int i = tid; i < HID * OUTSZ / 4; i += THR2) ws[i] = wg[i];
        if (tid < OUTSZ) sh_bout[tid] = bout[tid];
    }

    // xp prefetch geometry: 256 threads each copy one float4 of the [16][64] tile
    const int xb = tid >> 4, xq = tid & 15;
    const float* xsrc0 = g_xproj + (size_t)(b0 + xb) * HID + jbase + xq * 4;
    const uint32_t xp_smem0 = smem_u32(sh_xp) + (uint32_t)(xb * 64 + xq * 4) * 4;
    if (tid < 256) cp16_cg(xp_smem0, xsrc0);
    cp_commit();

    // oproj mapping: oo = out col, orow = 1 of 2 rows for this rank, oks: 16 x 32k
    const int oo   = tid & 31;
    const int orow = 2 * rank + ((tid >> 5) & 1);
    const int oks  = tid >> 6;

    // A-frag base pointer: row = lane/4, col = lane%4 within this kq's range
    const float* apA = sh_h + (lane >> 2) * HPAD + kq * 128 + (lane & 3);

    for (int s = 0; s < TSTEPS; ++s) {
        // ---- load H_s (16x512 -> padded smem rows of HPAD) ----
        if (s == 0) {
            float4 z = make_float4(0.f, 0.f, 0.f, 0.f);
#pragma unroll
            for (int u = 0; u < 2; u++) {
                int i = tid + THR2 * u;
                sh_h4[(i >> 7) * 129 + (i & 127)] = z;
            }
        } else {
            const float4* hs = (const float4*)(g_h[s & 1] + (size_t)b0 * HID);
#pragma unroll
            for (int u = 0; u < 2; u++) {
                int i = tid + THR2 * u;
                sh_h4[(i >> 7) * 129 + (i & 127)] = __ldcv(hs + i);
            }
        }
        cp_wait_all();          // xp(s) landed in buffer s&1
        __syncthreads();        // sync1: sh_h + xp ready

        // prefetch xp(s+1)
        if (s + 1 < TSTEPS && tid < 256)
            cp16_cg(xp_smem0 + ((s + 1) & 1) * 4096,
                    xsrc0 + (size_t)(s + 1) * BATCH * HID);
        cp_commit();

        // ---- output projection (accumulate) for step s-1: reads sh_h only ----
        if (s > 0) {
            const float4* hr4 = (const float4*)(sh_h + orow * HPAD + oks * 32);
            const float*  wc  = sh_wout + oks * 32 * OUTSZ + oo;
            float oa = 0.f;
#pragma unroll
            for (int k4 = 0; k4 < 8; k4++) {
                float4 hv = hr4[k4];
                oa = fmaf(hv.x, wc[(k4 * 4 + 0) * OUTSZ], oa);
                oa = fmaf(hv.y, wc[(k4 * 4 + 1) * OUTSZ], oa);
                oa = fmaf(hv.z, wc[(k4 * 4 + 2) * OUTSZ], oa);
                oa = fmaf(hv.w, wc[(k4 * 4 + 3) * OUTSZ], oa);
            }
            sh_opart[oks * 64 + (tid & 63)] = oa;
        }

        // ---- recurrent matmul: 16 tf32 MMAs (m16 b x n8 j x k8), k = kq*128.. ----
        {
            float c0 = 0.f, c1 = 0.f, c2 = 0.f, c3 = 0.f;
#pragma unroll
            for (int kk = 0; kk < 16; kk++) {
                uint32_t a0 = to_tf32(apA[kk * 8]);
                uint32_t a1 = to_tf32(apA[kk * 8 + 8 * HPAD]);
                uint32_t a2 = to_tf32(apA[kk * 8 + 4]);
                uint32_t a3 = to_tf32(apA[kk * 8 + 8 * HPAD + 4]);
                mma_tf32(c0, c1, c2, c3, a0, a1, a2, a3, Bf[kk][0], Bf[kk][1]);
            }
            // D layout: c0,c1 -> (row=lane/4,   col=(lane%4)*2, +1)
            //           c2,c3 -> (row=lane/4+8, col same)
            const int bb = lane >> 2;
            const int jj = noct * 8 + (lane & 3) * 2;
            *(float2*)&sh_part[(kq * 16 + bb    ) * 64 + jj] = make_float2(c0, c1);
            *(float2*)&sh_part[(kq * 16 + bb + 8) * 64 + jj] = make_float2(c2, c3);
        }
        __syncthreads();        // sync2: sh_part + sh_opart ready

        // ---- state update: one (b,j) element per thread ----
        {
            const int b = tid >> 6, j = tid & 63;
            float pre = (sh_part[(b     ) * 64 + j] + sh_part[(16 + b) * 64 + j])
                      + (sh_part[(32 + b) * 64 + j] + sh_part[(48 + b) * 64 + j]);
            const float* xp_cur = sh_xp + (s & 1) * 1024;
            float act = pre + xp_cur[b * 64 + j];
            act = act > 0.f ? act : 0.f;
            float hn = 0.999f * sh_h[b * HPAD + jbase + j] + 0.001f * act;
            g_h[(s + 1) & 1][(size_t)(b0 + b) * HID + jbase + j] = hn;
        }
        // ---- output projection (finalize) for step s-1 ----
        if (s > 0 && tid < 64) {
            float v = sh_bout[tid & 31];
#pragma unroll
            for (int k = 0; k < 16; k++) v += sh_opart[k * 64 + tid];
            int row = b0 + 2 * rank + (tid >> 5);
            out[((size_t)(s - 1) * BATCH + row) * OUTSZ + (tid & 31)] = v;
        }

        // cluster barrier: release publishes g_h stores; peers read via __ldcv
        asm volatile("barrier.cluster.arrive.aligned;" ::: "memory");
        asm volatile("barrier.cluster.wait.aligned;"   ::: "memory");
    }

    // ---- epilogue: out[1023] from H_1024 (in g_h[0]) ----
    {
        const float4* hs = (const float4*)(g_h[0] + (size_t)b0 * HID);
#pragma unroll
        for (int u = 0; u < 2; u++) {
            int i = tid + THR2 * u;
            sh_h4[(i >> 7) * 129 + (i & 127)] = __ldcv(hs + i);
        }
        __syncthreads();
        {
            const float4* hr4 = (const float4*)(sh_h + orow * HPAD + oks * 32);
            const float*  wc  = sh_wout + oks * 32 * OUTSZ + oo;
            float oa = 0.f;
#pragma unroll
            for (int k4 = 0; k4 < 8; k4++) {
                float4 hv = hr4[k4];
                oa = fmaf(hv.x, wc[(k4 * 4 + 0) * OUTSZ], oa);
                oa = fmaf(hv.y, wc[(k4 * 4 + 1) * OUTSZ], oa);
                oa = fmaf(hv.z, wc[(k4 * 4 + 2) * OUTSZ], oa);
                oa = fmaf(hv.w, wc[(k4 * 4 + 3) * OUTSZ], oa);
            }
            sh_opart[oks * 64 + (tid & 63)] = oa;
        }
        __syncthreads();
        if (tid < 64) {
            float v = sh_bout[tid & 31];
#pragma unroll
            for (int k = 0; k < 16; k++) v += sh_opart[k * 64 + tid];
            int row = b0 + 2 * rank + (tid >> 5);
            out[((size_t)(TSTEPS - 1) * BATCH + row) * OUTSZ + (tid & 31)] = v;
        }
    }
}

// ---------------------------------------------------------------------------
extern "C" void kernel_launch(void* const* d_in, const int* in_sizes, int n_in,
                              void* d_out, int out_size)
{
    const float* inputs = (const float*)d_in[0];
    const float* Wrec   = (const float*)d_in[1];
    const float* Win    = (const float*)d_in[2];
    const float* brec   = (const float*)d_in[3];
    const float* Wout   = (const float*)d_in[4];
    const float* bout   = (const float*)d_in[5];
    float* out = (float*)d_out;

    const int smem1 = (128 * 132 + 128 * 128) * 4;   // 133120
    cudaFuncSetAttribute(xproj_kernel, cudaFuncAttributeMaxDynamicSharedMemorySize, smem1);
    cudaFuncSetAttribute(rnn_kernel,   cudaFuncAttributeMaxDynamicSharedMemorySize, SM2_BYTES);

    dim3 g1((TSTEPS * BATCH) / 128, HID / 128);
    xproj_kernel<<<g1, 256, smem1>>>(inputs, Win, brec);

    rnn_kernel<<<128, THR2, SM2_BYTES>>>(Wrec, Wout, bout, out);

    (void)in_sizes; (void)n_in; (void)out_size;
}